// round 3
// baseline (speedup 1.0000x reference)
#include <cuda_runtime.h>
#include <cstdint>
#include <cstddef>

// ---------------------------------------------------------------------------
// RGCN (2 layers) restructured:
//   layer(x) = [mean_{r}(x[src] over edges(dst,r)) for r<8, x] @ vstack(W,root) + b
//   final lin folded into layer-2 weights.
// Pipeline per call:
//   CSR build (hist -> scan -> fill)            [int atomics only]
//   weight builds (Wcat1 copy, Wcat2 @ lin_W fold, bias fold)
//   L1: aggregate -> Xcat ; GEMM tf32 (relu) -> H
//   L2: aggregate(H) -> Xcat ; GEMM tf32 -> out
// ---------------------------------------------------------------------------

#define NNODES 50000
#define NEDGES 1000000
#define CDIM   128
#define NREL   8
#define NRSEG  (NNODES * NREL)          // 400000 segments
#define KDIM   (CDIM * (NREL + 1))      // 1152
#define SCAN_CHUNK 1024
#define NSCAN_BLOCKS ((NRSEG + SCAN_CHUNK - 1) / SCAN_CHUNK)   // 391

// ---- scratch (device globals; no runtime allocation allowed) ----
__device__ int   g_deg[NRSEG];
__device__ int   g_off[NRSEG + 1];
__device__ int   g_cur[NRSEG];
__device__ int   g_bsum[512];
__device__ int   g_bscan[512];
__device__ int   g_esrc[NEDGES];
__device__ float g_xcat[(size_t)NNODES * KDIM];   // 230.4 MB
__device__ float g_h[(size_t)NNODES * CDIM];      // 25.6 MB
__device__ float g_w1[KDIM * CDIM];
__device__ float g_w2[KDIM * CDIM];
__device__ float g_b2[CDIM];

// ---------------------------------------------------------------------------
// CSR build
// ---------------------------------------------------------------------------
__global__ void zero_deg_kernel() {
    int i = blockIdx.x * blockDim.x + threadIdx.x;
    if (i < NRSEG) g_deg[i] = 0;
}

__global__ void hist_kernel(const int* __restrict__ dst, const int* __restrict__ et) {
    int e = blockIdx.x * blockDim.x + threadIdx.x;
    if (e >= NEDGES) return;
    atomicAdd(&g_deg[dst[e] * NREL + et[e]], 1);
}

__global__ void scan1_kernel() {
    __shared__ int sh[256];
    int t = threadIdx.x;
    int base = blockIdx.x * SCAN_CHUNK + t * 4;
    int v[4];
    int s = 0;
#pragma unroll
    for (int j = 0; j < 4; j++) {
        int idx = base + j;
        v[j] = (idx < NRSEG) ? g_deg[idx] : 0;
        s += v[j];
    }
    sh[t] = s;
    __syncthreads();
    for (int off = 1; off < 256; off <<= 1) {
        int x = (t >= off) ? sh[t - off] : 0;
        __syncthreads();
        sh[t] += x;
        __syncthreads();
    }
    int incl = sh[t];
    int run = incl - s;               // exclusive prefix of this thread
    if (t == 255) g_bsum[blockIdx.x] = incl;
#pragma unroll
    for (int j = 0; j < 4; j++) {
        int idx = base + j;
        if (idx < NRSEG) g_off[idx] = run;
        run += v[j];
    }
}

__global__ void scan2_kernel() {
    __shared__ int sh[512];
    int t = threadIdx.x;
    int v = (t < NSCAN_BLOCKS) ? g_bsum[t] : 0;
    sh[t] = v;
    __syncthreads();
    for (int off = 1; off < 512; off <<= 1) {
        int x = (t >= off) ? sh[t - off] : 0;
        __syncthreads();
        sh[t] += x;
        __syncthreads();
    }
    if (t < NSCAN_BLOCKS) g_bscan[t] = sh[t] - v;
    if (t == NSCAN_BLOCKS - 1) g_off[NRSEG] = sh[t];   // total = NEDGES
}

__global__ void scan3_kernel() {
    int i = blockIdx.x * blockDim.x + threadIdx.x;
    if (i >= NRSEG) return;
    int v = g_off[i] + g_bscan[i / SCAN_CHUNK];
    g_off[i] = v;
    g_cur[i] = v;
}

__global__ void fill_kernel(const int* __restrict__ src, const int* __restrict__ dst,
                            const int* __restrict__ et) {
    int e = blockIdx.x * blockDim.x + threadIdx.x;
    if (e >= NEDGES) return;
    int seg = dst[e] * NREL + et[e];
    int pos = atomicAdd(&g_cur[seg], 1);
    g_esrc[pos] = src[e];
}

// ---------------------------------------------------------------------------
// Weight builds
// ---------------------------------------------------------------------------
__global__ void buildw1_kernel(const float* __restrict__ W1, const float* __restrict__ root1) {
    int i = blockIdx.x * blockDim.x + threadIdx.x;
    if (i >= KDIM * CDIM) return;
    const int cut = NREL * CDIM * CDIM;
    g_w1[i] = (i < cut) ? W1[i] : root1[i - cut];
}

// Wcat2'[k][j] = sum_c vstack(W2,root2)[k][c] * linW[c][j]
__global__ void foldw2_kernel(const float* __restrict__ W2, const float* __restrict__ root2,
                              const float* __restrict__ linW) {
    __shared__ float rs[CDIM];
    int k = blockIdx.x;
    int j = threadIdx.x;
    const float* row = (k < NREL * CDIM) ? (W2 + (size_t)k * CDIM)
                                         : (root2 + (size_t)(k - NREL * CDIM) * CDIM);
    rs[j] = row[j];
    __syncthreads();
    float s = 0.f;
#pragma unroll 8
    for (int c = 0; c < CDIM; c++) s += rs[c] * linW[c * CDIM + j];
    g_w2[(size_t)k * CDIM + j] = s;
}

__global__ void foldb2_kernel(const float* __restrict__ b2, const float* __restrict__ linW,
                              const float* __restrict__ linb) {
    int j = threadIdx.x;
    float s = linb[j];
#pragma unroll 8
    for (int c = 0; c < CDIM; c++) s += b2[c] * linW[c * CDIM + j];
    g_b2[j] = s;
}

// ---------------------------------------------------------------------------
// Segment mean aggregation: one warp per (node, rel) segment -> g_xcat
// ---------------------------------------------------------------------------
__global__ void aggregate_kernel(const float* __restrict__ feat) {
    int wid = (blockIdx.x * blockDim.x + threadIdx.x) >> 5;
    if (wid >= NRSEG) return;
    int lane = threadIdx.x & 31;
    int beg = g_off[wid];
    int end = g_off[wid + 1];
    float4 acc = make_float4(0.f, 0.f, 0.f, 0.f);
    for (int i = beg; i < end; i++) {
        int s = g_esrc[i];
        float4 v = reinterpret_cast<const float4*>(feat + (size_t)s * CDIM)[lane];
        acc.x += v.x; acc.y += v.y; acc.z += v.z; acc.w += v.w;
    }
    float inv = (end > beg) ? 1.0f / (float)(end - beg) : 0.0f;
    acc.x *= inv; acc.y *= inv; acc.z *= inv; acc.w *= inv;
    int v = wid >> 3;         // node
    int r = wid & 7;          // relation
    reinterpret_cast<float4*>(g_xcat + (size_t)v * KDIM + r * CDIM)[lane] = acc;
}

// copy feat into trailing CDIM columns of Xcat (root-transform operand)
__global__ void copyfeat_kernel(const float* __restrict__ feat) {
    int idx = blockIdx.x * blockDim.x + threadIdx.x;
    if (idx >= NNODES * (CDIM / 4)) return;
    int v = idx >> 5;
    int c = idx & 31;
    reinterpret_cast<float4*>(g_xcat + (size_t)v * KDIM + NREL * CDIM)[c] =
        reinterpret_cast<const float4*>(feat)[idx];
}

// ---------------------------------------------------------------------------
// tf32 GEMM: C[NNODES,128] = A[NNODES,1152] @ B[1152,128] + bias  (opt. relu)
// Block tile 128x128, BK=16, 8 warps (each 64x32), mma.sync m16n8k8 tf32,
// cp.async double-buffered, conflict-free padded smem.
// ---------------------------------------------------------------------------
__device__ __forceinline__ void cpa16(void* smem, const void* gmem, bool pred) {
    uint32_t s = (uint32_t)__cvta_generic_to_shared(smem);
    int sz = pred ? 16 : 0;
    asm volatile("cp.async.cg.shared.global [%0], [%1], 16, %2;\n"
                 :: "r"(s), "l"(gmem), "r"(sz));
}

__device__ __forceinline__ uint32_t tf32cvt(float x) {
    uint32_t u;
    asm("cvt.rna.tf32.f32 %0, %1;" : "=r"(u) : "f"(x));
    return u;
}

__device__ __forceinline__ void mma8(float* c, const uint32_t* a, const uint32_t* b) {
    asm volatile(
        "mma.sync.aligned.m16n8k8.row.col.f32.tf32.tf32.f32 "
        "{%0,%1,%2,%3}, {%4,%5,%6,%7}, {%8,%9}, {%0,%1,%2,%3};"
        : "+f"(c[0]), "+f"(c[1]), "+f"(c[2]), "+f"(c[3])
        : "r"(a[0]), "r"(a[1]), "r"(a[2]), "r"(a[3]), "r"(b[0]), "r"(b[1]));
}

template <int RELU>
__global__ __launch_bounds__(256)
void gemm_kernel(const float* __restrict__ A, const float* __restrict__ B,
                 const float* __restrict__ bias, float* __restrict__ C) {
    __shared__ float As[2][128 * 20];   // stride 20: (20*m+k)%32 distinct over frag
    __shared__ float Bs[2][16 * 132];   // stride 132: (132*k+n)%32 distinct over frag

    const int tid = threadIdx.x;
    const int lane = tid & 31;
    const int warp = tid >> 5;
    const int wm = (warp & 1) * 64;
    const int wn = (warp >> 1) * 32;
    const int blockRow = blockIdx.x * 128;
    const int gid = lane >> 2;
    const int tg = lane & 3;

    float acc[4][4][4];
#pragma unroll
    for (int a = 0; a < 4; a++)
#pragma unroll
        for (int b = 0; b < 4; b++)
#pragma unroll
            for (int c = 0; c < 4; c++) acc[a][b][c] = 0.f;

    const int ar = tid >> 2;          // 0..63 (A rows ar and ar+64)
    const int ac = (tid & 3) * 4;     // float4 col in BK
    const int br = tid >> 5;          // 0..7  (B rows br and br+8)
    const int bc = (tid & 31) * 4;

    auto stage = [&](int kt, int buf) {
        int g0 = blockRow + ar;
        int g1 = g0 + 64;
        cpa16(&As[buf][ar * 20 + ac],        A + (size_t)g0 * KDIM + kt * 16 + ac, g0 < NNODES);
        cpa16(&As[buf][(ar + 64) * 20 + ac], A + (size_t)g1 * KDIM + kt * 16 + ac, g1 < NNODES);
        cpa16(&Bs[buf][br * 132 + bc],       B + (size_t)(kt * 16 + br) * CDIM + bc, true);
        cpa16(&Bs[buf][(br + 8) * 132 + bc], B + (size_t)(kt * 16 + br + 8) * CDIM + bc, true);
        asm volatile("cp.async.commit_group;");
    };

    constexpr int NKT = KDIM / 16;    // 72
    stage(0, 0);
    for (int kt = 0; kt < NKT; kt++) {
        int buf = kt & 1;
        if (kt + 1 < NKT) {
            stage(kt + 1, buf ^ 1);
            asm volatile("cp.async.wait_group 1;");
        } else {
            asm volatile("cp.async.wait_group 0;");
        }
        __syncthreads();

        const float* as = As[buf];
        const float* bs = Bs[buf];
#pragma unroll
        for (int ks = 0; ks < 16; ks += 8) {
            uint32_t af[4][4], bf[4][2];
#pragma unroll
            for (int mi = 0; mi < 4; mi++) {
                int r = wm + mi * 16 + gid;
                af[mi][0] = tf32cvt(as[r * 20 + ks + tg]);
                af[mi][1] = tf32cvt(as[(r + 8) * 20 + ks + tg]);
                af[mi][2] = tf32cvt(as[r * 20 + ks + tg + 4]);
                af[mi][3] = tf32cvt(as[(r + 8) * 20 + ks + tg + 4]);
            }
#pragma unroll
            for (int ni = 0; ni < 4; ni++) {
                int n = wn + ni * 8 + gid;
                bf[ni][0] = tf32cvt(bs[(ks + tg) * 132 + n]);
                bf[ni][1] = tf32cvt(bs[(ks + tg + 4) * 132 + n]);
            }
#pragma unroll
            for (int mi = 0; mi < 4; mi++)
#pragma unroll
                for (int ni = 0; ni < 4; ni++) mma8(acc[mi][ni], af[mi], bf[ni]);
        }
        __syncthreads();
    }

    // epilogue: bias (+relu), guarded float2 stores
#pragma unroll
    for (int mi = 0; mi < 4; mi++) {
        int r0 = blockRow + wm + mi * 16 + gid;
        int r1 = r0 + 8;
#pragma unroll
        for (int ni = 0; ni < 4; ni++) {
            int col = wn + ni * 8 + tg * 2;
            float b0 = bias[col], b1 = bias[col + 1];
            float v0 = acc[mi][ni][0] + b0;
            float v1 = acc[mi][ni][1] + b1;
            float v2 = acc[mi][ni][2] + b0;
            float v3 = acc[mi][ni][3] + b1;
            if (RELU) {
                v0 = fmaxf(v0, 0.f); v1 = fmaxf(v1, 0.f);
                v2 = fmaxf(v2, 0.f); v3 = fmaxf(v3, 0.f);
            }
            if (r0 < NNODES) {
                float2 t; t.x = v0; t.y = v1;
                *reinterpret_cast<float2*>(C + (size_t)r0 * CDIM + col) = t;
            }
            if (r1 < NNODES) {
                float2 t; t.x = v2; t.y = v3;
                *reinterpret_cast<float2*>(C + (size_t)r1 * CDIM + col) = t;
            }
        }
    }
}

// ---------------------------------------------------------------------------
extern "C" void kernel_launch(void* const* d_in, const int* in_sizes, int n_in,
                              void* d_out, int out_size) {
    const float* x     = (const float*)d_in[0];
    const int*   ei    = (const int*)  d_in[1];
    const int*   et    = (const int*)  d_in[2];
    const float* W1    = (const float*)d_in[3];
    const float* root1 = (const float*)d_in[4];
    const float* b1    = (const float*)d_in[5];
    const float* W2    = (const float*)d_in[6];
    const float* root2 = (const float*)d_in[7];
    const float* b2    = (const float*)d_in[8];
    const float* linW  = (const float*)d_in[9];
    const float* linb  = (const float*)d_in[10];
    float* out = (float*)d_out;

    const int* src = ei;
    const int* dst = ei + NEDGES;

    float *p_xcat, *p_h, *p_w1, *p_w2, *p_b2;
    cudaGetSymbolAddress((void**)&p_xcat, g_xcat);
    cudaGetSymbolAddress((void**)&p_h,    g_h);
    cudaGetSymbolAddress((void**)&p_w1,   g_w1);
    cudaGetSymbolAddress((void**)&p_w2,   g_w2);
    cudaGetSymbolAddress((void**)&p_b2,   g_b2);

    // CSR build (shared by both layers)
    zero_deg_kernel<<<(NRSEG + 255) / 256, 256>>>();
    hist_kernel<<<(NEDGES + 255) / 256, 256>>>(dst, et);
    scan1_kernel<<<NSCAN_BLOCKS, 256>>>();
    scan2_kernel<<<1, 512>>>();
    scan3_kernel<<<(NRSEG + 255) / 256, 256>>>();
    fill_kernel<<<(NEDGES + 255) / 256, 256>>>(src, dst, et);

    // weights
    buildw1_kernel<<<(KDIM * CDIM + 255) / 256, 256>>>(W1, root1);
    foldw2_kernel<<<KDIM, CDIM>>>(W2, root2, linW);
    foldb2_kernel<<<1, CDIM>>>(b2, linW, linb);

    // layer 1
    aggregate_kernel<<<NRSEG / 8, 256>>>(x);
    copyfeat_kernel<<<(NNODES * 32 + 255) / 256, 256>>>(x);
    gemm_kernel<1><<<(NNODES + 127) / 128, 256>>>(p_xcat, p_w1, b1, p_h);

    // layer 2 (final linear folded into weights)
    aggregate_kernel<<<NRSEG / 8, 256>>>(p_h);
    copyfeat_kernel<<<(NNODES * 32 + 255) / 256, 256>>>(p_h);
    gemm_kernel<0><<<(NNODES + 127) / 128, 256>>>(p_xcat, p_w2, p_b2, out);
}